// round 11
// baseline (speedup 1.0000x reference)
#include <cuda_runtime.h>
#include <cuda_bf16.h>
#include <cfloat>

#define NA 8400
#define NB 32
#define NT 50
#define NK 10
#define NC 80
#define NCAND 108
#define NBLK 152            // one block per SM, one wave
#define NWARP 11            // 152*11 = 1672 >= 1600 targets
#define NTHR (NWARP * 32)   // 352
#define MAXPOS (NB * NT * NK)
#define NV4 67200           // obj elements as float4 (268800/4)
#define GTHREADS (NBLK * NTHR)  // 53504

// ---- persistent scratch (device globals; zero at load, every launch restores zero) ----
__device__ int      g_flag[NB * NA];
__device__ int      g_list[MAXPOS];
__device__ unsigned g_cnt;
__device__ unsigned g_done;
__device__ double   g_acc[4];   // 0:num_pos 1:reg_sum 2:cls_sum 3:obj_sum

// ---- f32x2 packed helpers (sm_103a) ----
__device__ __forceinline__ unsigned long long pk2(float a, float b) {
    unsigned long long r;
    asm("mov.b64 %0, {%1, %2};" : "=l"(r) : "r"(__float_as_uint(a)), "r"(__float_as_uint(b)));
    return r;
}
__device__ __forceinline__ void upk2(unsigned long long v, float& a, float& b) {
    unsigned ia, ib;
    asm("mov.b64 {%0, %1}, %2;" : "=r"(ia), "=r"(ib) : "l"(v));
    a = __uint_as_float(ia); b = __uint_as_float(ib);
}
__device__ __forceinline__ unsigned long long fma2_(unsigned long long a, unsigned long long b, unsigned long long c) {
    unsigned long long d;
    asm("fma.rn.f32x2 %0, %1, %2, %3;" : "=l"(d) : "l"(a), "l"(b), "l"(c));
    return d;
}
__device__ __forceinline__ unsigned long long add2_(unsigned long long a, unsigned long long b) {
    unsigned long long d;
    asm("add.rn.f32x2 %0, %1, %2;" : "=l"(d) : "l"(a), "l"(b));
    return d;
}
__device__ __forceinline__ float ex2f(float m) {   // 2^m, 1 MUFU
    float y; asm("ex2.approx.f32 %0, %1;" : "=f"(y) : "f"(m)); return y;
}

// packed softplus-pair accumulate: acc2 += softplus(xa),softplus(xb)
// softplus(x) = 0.5*(x+|x|) + ln(1+e^-|x|), ln(1+y) ~ y*P5(y), |err| <= ~2e-5
struct SPK { unsigned long long e1, e2, e3, e4, e5, half; };
__device__ __forceinline__ unsigned long long sp2_acc(unsigned long long acc2, float xa, float xb, const SPK& k) {
    const float L2E = 1.4426950408889634f;
    float ta = fabsf(xa), tb = fabsf(xb);
    float ya = ex2f(ta * -L2E);
    float yb = ex2f(tb * -L2E);
    unsigned long long y2 = pk2(ya, yb);
    unsigned long long q = fma2_(y2, k.e5, k.e4);
    q = fma2_(y2, q, k.e3);
    q = fma2_(y2, q, k.e2);
    q = fma2_(y2, q, k.e1);
    unsigned long long r2 = pk2(xa + ta, xb + tb);   // 2*relu
    acc2 = fma2_(r2, k.half, acc2);
    acc2 = fma2_(y2, q, acc2);
    return acc2;
}

__device__ __forceinline__ int win_base(float tc, float s, int W) {
    float u = tc / s - 0.5f;
    int f = (int)floorf(u) - 2;
    if (f < 0) f = 0;
    if (f > W - 6) f = W - 6;
    return f;
}

__global__ void __launch_bounds__(NTHR) k_main(
    const float* __restrict__ p3_cls, const float* __restrict__ p3_reg, const float* __restrict__ p3_obj,
    const float* __restrict__ p4_cls, const float* __restrict__ p4_reg, const float* __restrict__ p4_obj,
    const float* __restrict__ p5_cls, const float* __restrict__ p5_reg, const float* __restrict__ p5_obj,
    const float* __restrict__ targets, float* __restrict__ out)
{
    const unsigned FULL = 0xffffffffu;
    int lane = threadIdx.x & 31;
    int wid  = threadIdx.x >> 5;

    __shared__ const float* s_ptr[NWARP][NK];   // winner cls base ptr
    __shared__ int          s_hw [NWARP][NK];   // class stride (elements)
    __shared__ float s_np[16], s_rg[16], s_cl[16], s_ob[16];

    SPK K;
    K.e1 = pk2( 0.999232f,   0.999232f);
    K.e2 = pk2(-0.490229f,  -0.490229f);
    K.e3 = pk2( 0.285283f,   0.285283f);
    K.e4 = pk2(-0.1315968f, -0.1315968f);
    K.e5 = pk2( 0.03045376f, 0.03045376f);
    K.half = pk2(0.5f, 0.5f);

    float w_np = 0.f, w_rg = 0.f, w_cl = 0.f, w_ob = 0.f;   // lane0-held warp results

    int wg = blockIdx.x * NWARP + wid;
    if (wg < NB * NT) {
        // ======== assignment: one warp per (b,t) ========
        int b = wg / NT;
        const float* tgt = targets + wg * 5;
        float tw = tgt[2], th = tgt[3];
        float tcx = tgt[0] + 0.5f * tw;
        float tcy = tgt[1] + 0.5f * th;
        int tcls = (int)tgt[4];

        int x0a = win_base(tcx,  8.f, 80), y0a = win_base(tcy,  8.f, 80);
        int x0b = win_base(tcx, 16.f, 40), y0b = win_base(tcy, 16.f, 40);
        int x0c = win_base(tcx, 32.f, 20), y0c = win_base(tcy, 32.f, 20);

        // per-lane sorted-4 candidates (asc by (dist, idx)); 6x6/level window
        // provably contains each level's top-10, hence the global top-10
        float cd[4]; int ci[4];
#pragma unroll
        for (int j = 0; j < 4; j++) { cd[j] = FLT_MAX; ci[j] = 0x7FFFFFFF; }
#pragma unroll
        for (int t = 0; t < 4; t++) {
            int c = lane + (t << 5);
            if (c >= NCAND) break;
            int lvl = (c >= 72) ? 2 : (c >= 36) ? 1 : 0;
            int w6 = c - 36 * lvl;
            int dxi = w6 % 6, dyi = w6 / 6;
            int gx, gy, W, basei; float s;
            if (lvl == 0)      { gx = x0a + dxi; gy = y0a + dyi; W = 80; basei = 0;    s = 8.f;  }
            else if (lvl == 1) { gx = x0b + dxi; gy = y0b + dyi; W = 40; basei = 6400; s = 16.f; }
            else               { gx = x0c + dxi; gy = y0c + dyi; W = 20; basei = 8000; s = 32.f; }
            int idx = basei + gy * W + gx;
            float acx = (float)gx * s + 0.5f * s;
            float acy = (float)gy * s + 0.5f * s;
            float dx = __fsub_rn(acx, tcx);
            float dy = __fsub_rn(acy, tcy);
            float dist = __fsqrt_rn(__fadd_rn(__fmul_rn(dx, dx), __fmul_rn(dy, dy)));
            float vcd = dist; int vci = idx;
#pragma unroll
            for (int j = 0; j < 4; j++) {
                bool sw = (vcd < cd[j]) || (vcd == cd[j] && vci < ci[j]);
                if (sw) { float td = cd[j]; int ti = ci[j]; cd[j] = vcd; ci[j] = vci; vcd = td; vci = ti; }
            }
        }

        // warp merge: 10 rounds of stable lexicographic min
        int res_a = 0;
#pragma unroll 1
        for (int k = 0; k < NK; k++) {
            float bd = cd[0]; int bi = ci[0];
#pragma unroll
            for (int off = 16; off; off >>= 1) {
                float od = __shfl_xor_sync(FULL, bd, off);
                int   oi = __shfl_xor_sync(FULL, bi, off);
                if (od < bd || (od == bd && oi < bi)) { bd = od; bi = oi; }
            }
            if (ci[0] == bi) {
#pragma unroll
                for (int j = 0; j < 3; j++) { cd[j] = cd[j + 1]; ci[j] = ci[j + 1]; }
                cd[3] = FLT_MAX; ci[3] = 0x7FFFFFFF;
            }
            if (lane == k) res_a = bi;
        }

        // lane k (<10): decode pred box, IoU + CIoU (selection-critical: precise math)
        bool have = (lane < NK);
        float iou = -FLT_MAX, ciou = 0.f;
        int my_a = res_a;
        int lvl = 0, gx = 0, gy = 0, W = 0, hw = 0; float s = 0.f;
        const float* clsp = p3_cls; const float* objp = p3_obj;
        if (have) {
            int a = my_a;
            if (a < 6400)      { lvl = 0; W = 80; hw = 6400; gx = a % 80;            gy = a / 80;            s = 8.f;  clsp = p3_cls; objp = p3_obj; }
            else if (a < 8000) { lvl = 1; W = 40; hw = 1600; int al = a - 6400; gx = al % 40; gy = al / 40; s = 16.f; clsp = p4_cls; objp = p4_obj; }
            else               { lvl = 2; W = 20; hw = 400;  int al = a - 8000; gx = al % 20; gy = al / 20; s = 32.f; clsp = p5_cls; objp = p5_obj; }
            const float* regp = (lvl == 0) ? p3_reg : (lvl == 1) ? p4_reg : p5_reg;
            int base = (b * 4) * hw + gy * W + gx;
            float r0 = regp[base];
            float r1 = regp[base + hw];
            float r2 = regp[base + 2 * hw];
            float r3 = regp[base + 3 * hw];
            float pcx = ((float)gx + 1.f / (1.f + expf(-r0))) * s;
            float pcy = ((float)gy + 1.f / (1.f + expf(-r1))) * s;
            float pw  = expf(r2) * s;
            float ph  = expf(r3) * s;
            float x11 = pcx - pw * 0.5f, x12 = pcx + pw * 0.5f;
            float y11 = pcy - ph * 0.5f, y12 = pcy + ph * 0.5f;
            float x21 = tcx - tw * 0.5f, x22 = tcx + tw * 0.5f;
            float y21 = tcy - th * 0.5f, y22 = tcy + th * 0.5f;
            float iw = fmaxf(fminf(x12, x22) - fmaxf(x11, x21), 0.f);
            float ih = fmaxf(fminf(y12, y22) - fmaxf(y11, y21), 0.f);
            float inter = iw * ih;
            float a1 = (x12 - x11) * (y12 - y11);
            float a2 = (x22 - x21) * (y22 - y21);
            float uni = a1 + a2 - inter + 1e-7f;
            iou = inter / uni;
            float cw  = fmaxf(x12, x22) - fminf(x11, x21);
            float chh = fmaxf(y12, y22) - fminf(y11, y21);
            float c2 = cw * cw + chh * chh + 1e-7f;
            float ddx = x21 + x22 - x11 - x12;
            float ddy = y21 + y22 - y11 - y12;
            float rho2 = (ddx * ddx + ddy * ddy) * 0.25f;
            float dv = atanf((x22 - x21) / ((y22 - y21) + 1e-7f))
                     - atanf((x12 - x11) / ((y12 - y11) + 1e-7f));
            float v = (float)(4.0 / (3.14159 * 3.14159)) * dv * dv;
            float alpha = v / ((1.f - iou) + v + 1e-7f);
            ciou = iou - (rho2 / c2 + v * alpha);
        }

        // argmax(iou) over K, first-max tie-break
        float am = iou; int amk = lane;
#pragma unroll
        for (int off = 16; off; off >>= 1) {
            float om = __shfl_xor_sync(FULL, am, off);
            int   ok = __shfl_xor_sync(FULL, amk, off);
            if (om > am || (om == am && ok < amk)) { am = om; amk = ok; }
        }

        unsigned vb = __ballot_sync(FULL, have && (iou > 0.1f));
        bool w = have && (vb ? (iou > 0.1f) : (lane == amk));
        unsigned wb = __ballot_sync(FULL, w);
        int npos = __popc(wb);

        float regc = w ? (1.f - ciou) : 0.f;
#pragma unroll
        for (int off = 16; off; off >>= 1) regc += __shfl_xor_sync(FULL, regc, off);

        // winners publish cls gather base + take x_tcls
        float xts = 0.f;
        const float* cbase = nullptr;
        if (w) {
            int r = __popc(wb & ((1u << lane) - 1));
            cbase = clsp + (size_t)(b * NC) * hw + gy * W + gx;
            s_ptr[wid][r] = cbase;
            s_hw [wid][r] = hw;
            xts = cbase[tcls * hw];
        }

        // obj correction: -x at each UNIQUE assigned (b,anchor); warp-aggregated g_cnt
        float corr = 0.f;
        bool newf = false;
        if (w) newf = (atomicExch(&g_flag[b * NA + my_a], 1) == 0);
        unsigned nb = __ballot_sync(FULL, newf);
        if (nb) {
            int leader = __ffs(nb) - 1;
            unsigned basep = 0;
            if (lane == leader) basep = atomicAdd(&g_cnt, (unsigned)__popc(nb));
            basep = __shfl_sync(FULL, basep, leader);
            if (newf) {
                g_list[basep + __popc(nb & ((1u << lane) - 1))] = b * NA + my_a;
                corr = -objp[b * hw + gy * W + gx];
            }
        }
        __syncwarp();

        // cls softplus sum: exact cover of npos*80 values in 25 batches (+1 pad)
        float xv[26];
#pragma unroll
        for (int j = 0; j < NK; j++) {
            bool aj = j < npos;
            const float* pj = aj ? s_ptr[wid][j] : nullptr;
            int hj = aj ? s_hw[wid][j] : 0;
            xv[2 * j]     = aj ? pj[lane * hj]        : -1e30f;
            xv[2 * j + 1] = aj ? pj[(lane + 32) * hj] : -1e30f;
        }
#pragma unroll
        for (int r = 0; r < 5; r++) {
            int j = 2 * r + (lane >> 4);
            int c = 64 + (lane & 15);
            bool aj = j < npos;
            xv[20 + r] = aj ? s_ptr[wid][j][c * s_hw[wid][j]] : -1e30f;
        }
        xv[25] = -1e30f;

        unsigned long long acc2 = 0ull;
#pragma unroll
        for (int q = 0; q < 13; q++)
            acc2 = sp2_acc(acc2, xv[2 * q], xv[2 * q + 1], K);
        float sa, sb; upk2(acc2, sa, sb);
        float clsn = (sa + sb) - xts;       // softplus sum minus one-hot term
#pragma unroll
        for (int off = 16; off; off >>= 1) {
            clsn += __shfl_xor_sync(FULL, clsn, off);
            corr += __shfl_xor_sync(FULL, corr, off);
        }
        if (lane == 0) { w_np = (float)npos; w_rg = regc; w_cl = clsn; w_ob = corr; }
    }

    // ======== background objectness: softplus over ALL B*A preds (balanced) ========
    {
        int v0 = blockIdx.x * NTHR + threadIdx.x;       // < 53504, always valid
        int v1 = v0 + GTHREADS;                          // maybe >= NV4
        float4 A, Bv;
        if (v0 < 51200)      A = ((const float4*)p3_obj)[v0];
        else if (v0 < 64000) A = ((const float4*)p4_obj)[v0 - 51200];
        else                 A = ((const float4*)p5_obj)[v0 - 64000];
        if (v1 < NV4) {
            if (v1 < 64000) Bv = ((const float4*)p4_obj)[v1 - 51200];
            else            Bv = ((const float4*)p5_obj)[v1 - 64000];
        } else {
            Bv = make_float4(-1e30f, -1e30f, -1e30f, -1e30f);
        }
        unsigned long long acc2 = 0ull;
        acc2 = sp2_acc(acc2, A.x, A.y, K);
        acc2 = sp2_acc(acc2, A.z, A.w, K);
        acc2 = sp2_acc(acc2, Bv.x, Bv.y, K);
        acc2 = sp2_acc(acc2, Bv.z, Bv.w, K);
        float sa, sb; upk2(acc2, sa, sb);
        float oacc = sa + sb;
#pragma unroll
        for (int off = 16; off; off >>= 1) oacc += __shfl_xor_sync(FULL, oacc, off);
        if (lane == 0) w_ob += oacc;
    }

    // ======== block reduction -> 4 double atomics ========
    if (lane == 0) { s_np[wid] = w_np; s_rg[wid] = w_rg; s_cl[wid] = w_cl; s_ob[wid] = w_ob; }
    if (wid == 0 && lane >= NWARP && lane < 16) { s_np[lane] = 0.f; s_rg[lane] = 0.f; s_cl[lane] = 0.f; s_ob[lane] = 0.f; }
    __syncthreads();
    if (wid == 0 && lane < 16) {
        float vnp = s_np[lane], vrg = s_rg[lane], vcl = s_cl[lane], vob = s_ob[lane];
#pragma unroll
        for (int off = 8; off; off >>= 1) {
            vnp += __shfl_xor_sync(0xffffu, vnp, off);
            vrg += __shfl_xor_sync(0xffffu, vrg, off);
            vcl += __shfl_xor_sync(0xffffu, vcl, off);
            vob += __shfl_xor_sync(0xffffu, vob, off);
        }
        if (lane == 0) {
            atomicAdd(&g_acc[0], (double)vnp);
            atomicAdd(&g_acc[1], (double)vrg);
            atomicAdd(&g_acc[2], (double)vcl);
            atomicAdd(&g_acc[3], (double)vob);
        }
    }

    // ======== last block finalizes + resets scratch ========
    __shared__ int s_last;
    __syncthreads();
    if (threadIdx.x == 0) {
        __threadfence();
        unsigned t = atomicAdd(&g_done, 1u);
        s_last = (t == gridDim.x - 1) ? 1 : 0;
    }
    __syncthreads();
    if (s_last) {
        __threadfence();
        unsigned cnt = g_cnt;
        for (unsigned i = threadIdx.x; i < cnt; i += NTHR)
            g_flag[g_list[i]] = 0;
        if (threadIdx.x == 0) {
            double np = atomicAdd(&g_acc[0], 0.0);
            double rg = atomicAdd(&g_acc[1], 0.0);
            double cl = atomicAdd(&g_acc[2], 0.0);
            double ob = atomicAdd(&g_acc[3], 0.0);
            if (np < 1.0) np = 1.0;
            double reg_l = rg / np, cls_l = cl / np, obj_l = ob / np;
            out[0] = (float)(5.0 * reg_l + obj_l + cls_l);
            out[1] = (float)reg_l;
            out[2] = (float)obj_l;
            out[3] = (float)cls_l;
            g_acc[0] = 0.0; g_acc[1] = 0.0; g_acc[2] = 0.0; g_acc[3] = 0.0;
            g_cnt = 0u; g_done = 0u;
        }
    }
}

extern "C" void kernel_launch(void* const* d_in, const int* in_sizes, int n_in,
                              void* d_out, int out_size) {
    const float* p3_cls  = (const float*)d_in[0];
    const float* p3_reg  = (const float*)d_in[1];
    const float* p3_obj  = (const float*)d_in[2];
    const float* p4_cls  = (const float*)d_in[3];
    const float* p4_reg  = (const float*)d_in[4];
    const float* p4_obj  = (const float*)d_in[5];
    const float* p5_cls  = (const float*)d_in[6];
    const float* p5_reg  = (const float*)d_in[7];
    const float* p5_obj  = (const float*)d_in[8];
    const float* targets = (const float*)d_in[9];

    k_main<<<NBLK, NTHR>>>(p3_cls, p3_reg, p3_obj,
                           p4_cls, p4_reg, p4_obj,
                           p5_cls, p5_reg, p5_obj,
                           targets, (float*)d_out);
}

// round 12
// speedup vs baseline: 1.2771x; 1.2771x over previous
#include <cuda_runtime.h>
#include <cuda_bf16.h>
#include <cfloat>

#define NA 8400
#define NB 32
#define NT 50
#define NK 10
#define NC 80
#define NCAND 108
#define NBLK 152            // resident one-wave grid (GB300: 152 SMs)
#define NTHR 512            // 16 warps
#define NWARPB 16
#define MAXPOS (NB * NT * NK)
#define GSTRIDE (NBLK * NTHR)   // 77824
#define OBJ_WARPS (NBLK * 5)    // warps 11..15 of each block: 760
#define OBJ_THREADS (OBJ_WARPS * 32)  // 24320
#define NV4 67200               // 268800 obj floats / 4

// ---- persistent scratch (zero at load; every launch restores zero) ----
__device__ unsigned g_win[MAXPOS];   // packed winner records (off|lvl<<24)
__device__ unsigned g_wcnt;          // winner count
__device__ int      g_flag[NB * NA]; // obj dedup flags (reset via g_list)
__device__ int      g_list[MAXPOS];
__device__ unsigned g_cnt;
__device__ unsigned g_done, g_done2;
__device__ double   g_acc[4];        // num_pos, reg_sum, cls_sum, obj_sum

__device__ __forceinline__ float ex2f(float m) {
    float y; asm("ex2.approx.f32 %0, %1;" : "=f"(y) : "f"(m)); return y;
}
// softplus(x) = relu(x) + ln(1+e^-|x|); ln(1+y) ~ y*P4(y) on [0,1], |err|~2e-5
__device__ __forceinline__ float splus(float x) {
    float t = fabsf(x);
    float y = ex2f(t * -1.4426950408889634f);
    float q = fmaf(y, 0.03045376f, -0.1315968f);
    q = fmaf(y, q, 0.285283f);
    q = fmaf(y, q, -0.490229f);
    q = fmaf(y, q, 0.999232f);
    return fmaxf(x, 0.f) + y * q;
}

__device__ __forceinline__ int win_base(float tc, float s, int W) {
    float u = tc / s - 0.5f;
    int f = (int)floorf(u) - 2;
    if (f < 0) f = 0;
    if (f > W - 6) f = W - 6;
    return f;
}

__global__ void __launch_bounds__(NTHR) k_main(
    const float* __restrict__ p3_cls, const float* __restrict__ p3_reg, const float* __restrict__ p3_obj,
    const float* __restrict__ p4_cls, const float* __restrict__ p4_reg, const float* __restrict__ p4_obj,
    const float* __restrict__ p5_cls, const float* __restrict__ p5_reg, const float* __restrict__ p5_obj,
    const float* __restrict__ targets, float* __restrict__ out)
{
    const unsigned FULL = 0xffffffffu;
    int lane = threadIdx.x & 31;
    int wid  = threadIdx.x >> 5;

    __shared__ float s_np[NWARPB], s_rg[NWARPB], s_cl[NWARPB], s_ob[NWARPB];
    __shared__ unsigned s_nw;
    float w_np = 0.f, w_rg = 0.f, w_cl = 0.f, w_ob = 0.f;

    int t = blockIdx.x + NBLK * wid;     // interleaved target mapping (balance)
    if (wid <= 10 && t < NB * NT) {
        // ================= PHASE 1: assignment, one warp per (b,t) =================
        int b = t / NT;
        const float* tgt = targets + t * 5;
        float tw = tgt[2], th = tgt[3];
        float tcx = tgt[0] + 0.5f * tw;
        float tcy = tgt[1] + 0.5f * th;
        int tcls = (int)tgt[4];

        int x0a = win_base(tcx,  8.f, 80), y0a = win_base(tcy,  8.f, 80);
        int x0b = win_base(tcx, 16.f, 40), y0b = win_base(tcy, 16.f, 40);
        int x0c = win_base(tcx, 32.f, 20), y0c = win_base(tcy, 32.f, 20);

        // per-lane sorted-4 of 108 window candidates (asc (dist, idx));
        // 6x6/level window provably contains the global top-10
        float cd[4]; int ci[4];
#pragma unroll
        for (int j = 0; j < 4; j++) { cd[j] = FLT_MAX; ci[j] = 0x7FFFFFFF; }
#pragma unroll
        for (int q = 0; q < 4; q++) {
            int c = lane + (q << 5);
            if (c >= NCAND) break;
            int lvl = (c >= 72) ? 2 : (c >= 36) ? 1 : 0;
            int w6 = c - 36 * lvl;
            int dxi = w6 % 6, dyi = w6 / 6;
            int gx, gy, W, basei; float s;
            if (lvl == 0)      { gx = x0a + dxi; gy = y0a + dyi; W = 80; basei = 0;    s = 8.f;  }
            else if (lvl == 1) { gx = x0b + dxi; gy = y0b + dyi; W = 40; basei = 6400; s = 16.f; }
            else               { gx = x0c + dxi; gy = y0c + dyi; W = 20; basei = 8000; s = 32.f; }
            int idx = basei + gy * W + gx;
            float acx = (float)gx * s + 0.5f * s;
            float acy = (float)gy * s + 0.5f * s;
            float dx = __fsub_rn(acx, tcx);
            float dy = __fsub_rn(acy, tcy);
            float dist = __fsqrt_rn(__fadd_rn(__fmul_rn(dx, dx), __fmul_rn(dy, dy)));
            float vcd = dist; int vci = idx;
#pragma unroll
            for (int j = 0; j < 4; j++) {
                bool sw = (vcd < cd[j]) || (vcd == cd[j] && vci < ci[j]);
                if (sw) { float td = cd[j]; int ti = ci[j]; cd[j] = vcd; ci[j] = vci; vcd = td; vci = ti; }
            }
        }

        // 10 rounds of stable lexicographic warp-min
        int res_a = 0;
#pragma unroll 1
        for (int k = 0; k < NK; k++) {
            float bd = cd[0]; int bi = ci[0];
#pragma unroll
            for (int off = 16; off; off >>= 1) {
                float od = __shfl_xor_sync(FULL, bd, off);
                int   oi = __shfl_xor_sync(FULL, bi, off);
                if (od < bd || (od == bd && oi < bi)) { bd = od; bi = oi; }
            }
            if (ci[0] == bi) {
#pragma unroll
                for (int j = 0; j < 3; j++) { cd[j] = cd[j + 1]; ci[j] = ci[j + 1]; }
                cd[3] = FLT_MAX; ci[3] = 0x7FFFFFFF;
            }
            if (lane == k) res_a = bi;
        }

        // lane k (<10): decode pred box, IoU + CIoU (precise math: selection-critical)
        bool have = (lane < NK);
        float iou = -FLT_MAX, ciou = 0.f;
        int my_a = res_a;
        int lvl = 0, gx = 0, gy = 0, W = 0, hw = 0; float s = 0.f;
        const float* clsp = p3_cls; const float* objp = p3_obj;
        if (have) {
            int a = my_a;
            if (a < 6400)      { lvl = 0; W = 80; hw = 6400; gx = a % 80;            gy = a / 80;            s = 8.f;  clsp = p3_cls; objp = p3_obj; }
            else if (a < 8000) { lvl = 1; W = 40; hw = 1600; int al = a - 6400; gx = al % 40; gy = al / 40; s = 16.f; clsp = p4_cls; objp = p4_obj; }
            else               { lvl = 2; W = 20; hw = 400;  int al = a - 8000; gx = al % 20; gy = al / 20; s = 32.f; clsp = p5_cls; objp = p5_obj; }
            const float* regp = (lvl == 0) ? p3_reg : (lvl == 1) ? p4_reg : p5_reg;
            int base = (b * 4) * hw + gy * W + gx;
            float r0 = regp[base];
            float r1 = regp[base + hw];
            float r2 = regp[base + 2 * hw];
            float r3 = regp[base + 3 * hw];
            float pcx = ((float)gx + 1.f / (1.f + expf(-r0))) * s;
            float pcy = ((float)gy + 1.f / (1.f + expf(-r1))) * s;
            float pw  = expf(r2) * s;
            float ph  = expf(r3) * s;
            float x11 = pcx - pw * 0.5f, x12 = pcx + pw * 0.5f;
            float y11 = pcy - ph * 0.5f, y12 = pcy + ph * 0.5f;
            float x21 = tcx - tw * 0.5f, x22 = tcx + tw * 0.5f;
            float y21 = tcy - th * 0.5f, y22 = tcy + th * 0.5f;
            float iw = fmaxf(fminf(x12, x22) - fmaxf(x11, x21), 0.f);
            float ih = fmaxf(fminf(y12, y22) - fmaxf(y11, y21), 0.f);
            float inter = iw * ih;
            float a1 = (x12 - x11) * (y12 - y11);
            float a2 = (x22 - x21) * (y22 - y21);
            float uni = a1 + a2 - inter + 1e-7f;
            iou = inter / uni;
            float cw  = fmaxf(x12, x22) - fminf(x11, x21);
            float chh = fmaxf(y12, y22) - fminf(y11, y21);
            float c2 = cw * cw + chh * chh + 1e-7f;
            float ddx = x21 + x22 - x11 - x12;
            float ddy = y21 + y22 - y11 - y12;
            float rho2 = (ddx * ddx + ddy * ddy) * 0.25f;
            float dv = atanf((x22 - x21) / ((y22 - y21) + 1e-7f))
                     - atanf((x12 - x11) / ((y12 - y11) + 1e-7f));
            float v = (float)(4.0 / (3.14159 * 3.14159)) * dv * dv;
            float alpha = v / ((1.f - iou) + v + 1e-7f);
            ciou = iou - (rho2 / c2 + v * alpha);
        }

        // argmax(iou), first-max tie-break
        float am = iou; int amk = lane;
#pragma unroll
        for (int off = 16; off; off >>= 1) {
            float om = __shfl_xor_sync(FULL, am, off);
            int   ok = __shfl_xor_sync(FULL, amk, off);
            if (om > am || (om == am && ok < amk)) { am = om; amk = ok; }
        }

        unsigned vb = __ballot_sync(FULL, have && (iou > 0.1f));
        bool w = have && (vb ? (iou > 0.1f) : (lane == amk));
        unsigned wb = __ballot_sync(FULL, w);
        int npos = __popc(wb);

        float regc = w ? (1.f - ciou) : 0.f;
#pragma unroll
        for (int off = 16; off; off >>= 1) regc += __shfl_xor_sync(FULL, regc, off);

        // winners: publish packed record, fold in -x_tcls, obj correction (dedup)
        float xts = 0.f;
        unsigned rec = 0; int clsoff = 0;
        if (w) {
            clsoff = (b * NC) * hw + gy * W + gx;        // < 2^24
            rec = (unsigned)clsoff | ((unsigned)lvl << 24);
            xts = clsp[clsoff + tcls * hw];              // one-hot term
        }
        // warp-aggregated record append
        {
            int leader = __ffs(wb) - 1;
            unsigned basep = 0;
            if (lane == leader) basep = atomicAdd(&g_wcnt, (unsigned)npos);
            basep = __shfl_sync(FULL, basep, leader);
            if (w) g_win[basep + __popc(wb & ((1u << lane) - 1))] = rec;
        }
        // obj correction at UNIQUE (b, anchor): bce(x,1)-bce(x,0) = -x
        float corr = 0.f;
        bool newf = false;
        if (w) newf = (atomicExch(&g_flag[b * NA + my_a], 1) == 0);
        unsigned nb2 = __ballot_sync(FULL, newf);
        if (nb2) {
            int leader = __ffs(nb2) - 1;
            unsigned basep = 0;
            if (lane == leader) basep = atomicAdd(&g_cnt, (unsigned)__popc(nb2));
            basep = __shfl_sync(FULL, basep, leader);
            if (newf) {
                g_list[basep + __popc(nb2 & ((1u << lane) - 1))] = b * NA + my_a;
                corr = -objp[b * hw + gy * W + gx];
            }
        }
        float neg = -xts + corr;
#pragma unroll
        for (int off = 16; off; off >>= 1) neg += __shfl_xor_sync(FULL, neg, off);
        // split: -xts belongs to cls_sum, corr to obj_sum; reduce separately
        float xsum = -xts;
#pragma unroll
        for (int off = 16; off; off >>= 1) xsum += __shfl_xor_sync(FULL, xsum, off);
        if (lane == 0) { w_np = (float)npos; w_rg = regc; w_cl = xsum; w_ob = neg - xsum; }
    } else if (wid >= 11) {
        // ========= PHASE 1 (parallel): background obj softplus over all B*A =========
        int ow = blockIdx.x * 5 + (wid - 11);
        int th = ow * 32 + lane;
        float o = 0.f;
#pragma unroll
        for (int q = 0; q < 3; q++) {
            int v = th + q * OBJ_THREADS;
            if (v < NV4) {
                const float4* p; int off;
                if (v < 51200)      { p = (const float4*)p3_obj; off = v; }
                else if (v < 64000) { p = (const float4*)p4_obj; off = v - 51200; }
                else                { p = (const float4*)p5_obj; off = v - 64000; }
                float4 x4 = p[off];
                o += splus(x4.x) + splus(x4.y) + splus(x4.z) + splus(x4.w);
            }
        }
#pragma unroll
        for (int off = 16; off; off >>= 1) o += __shfl_xor_sync(FULL, o, off);
        if (lane == 0) w_ob = o;
    }

    // ---- block reduction of phase-1 partials -> 4 double atomics ----
    if (lane == 0) { s_np[wid] = w_np; s_rg[wid] = w_rg; s_cl[wid] = w_cl; s_ob[wid] = w_ob; }
    __syncthreads();
    if (wid == 0 && lane < NWARPB) {
        float vnp = s_np[lane], vrg = s_rg[lane], vcl = s_cl[lane], vob = s_ob[lane];
#pragma unroll
        for (int off = 8; off; off >>= 1) {
            vnp += __shfl_xor_sync(0xffffu, vnp, off);
            vrg += __shfl_xor_sync(0xffffu, vrg, off);
            vcl += __shfl_xor_sync(0xffffu, vcl, off);
            vob += __shfl_xor_sync(0xffffu, vob, off);
        }
        if (lane == 0) {
            atomicAdd(&g_acc[0], (double)vnp);
            atomicAdd(&g_acc[1], (double)vrg);
            atomicAdd(&g_acc[2], (double)vcl);
            atomicAdd(&g_acc[3], (double)vob);
        }
    }

    // ---- device-wide soft barrier (all NBLK blocks resident: one wave) ----
    __syncthreads();
    if (threadIdx.x == 0) {
        __threadfence();
        atomicAdd(&g_done, 1u);
        while (atomicAdd(&g_done, 0u) < NBLK) { }
        s_nw = atomicAdd(&g_wcnt, 0u);
    }
    __syncthreads();

    // ================= PHASE 2: uniform cls softplus sweep =================
    {
        unsigned N2 = s_nw * NC;
        float cl2 = 0.f;
        for (unsigned i = blockIdx.x * NTHR + threadIdx.x; i < N2; i += GSTRIDE) {
            unsigned j = i / (unsigned)NC;
            unsigned c = i - j * NC;
            unsigned rec = g_win[j];
            unsigned off = rec & 0xFFFFFFu;
            unsigned lvl = rec >> 24;
            const float* base; int hw;
            if (lvl == 0)      { base = p3_cls; hw = 6400; }
            else if (lvl == 1) { base = p4_cls; hw = 1600; }
            else               { base = p5_cls; hw = 400;  }
            cl2 += splus(base[off + c * hw]);
        }
#pragma unroll
        for (int off = 16; off; off >>= 1) cl2 += __shfl_xor_sync(FULL, cl2, off);
        if (lane == 0) s_cl[wid] = cl2;
        __syncthreads();
        if (wid == 0 && lane < NWARPB) {
            float vcl = s_cl[lane];
#pragma unroll
            for (int off = 8; off; off >>= 1) vcl += __shfl_xor_sync(0xffffu, vcl, off);
            if (lane == 0) atomicAdd(&g_acc[2], (double)vcl);
        }
    }

    // ---- last block: finalize + reset all scratch ----
    __shared__ int s_last;
    __syncthreads();
    if (threadIdx.x == 0) {
        __threadfence();
        unsigned d = atomicAdd(&g_done2, 1u);
        s_last = (d == NBLK - 1) ? 1 : 0;
    }
    __syncthreads();
    if (s_last) {
        __threadfence();
        unsigned cnt = g_cnt;
        for (unsigned i = threadIdx.x; i < cnt; i += NTHR)
            g_flag[g_list[i]] = 0;
        if (threadIdx.x == 0) {
            double np = atomicAdd(&g_acc[0], 0.0);
            double rg = atomicAdd(&g_acc[1], 0.0);
            double cl = atomicAdd(&g_acc[2], 0.0);
            double ob = atomicAdd(&g_acc[3], 0.0);
            if (np < 1.0) np = 1.0;
            double reg_l = rg / np, cls_l = cl / np, obj_l = ob / np;
            out[0] = (float)(5.0 * reg_l + obj_l + cls_l);
            out[1] = (float)reg_l;
            out[2] = (float)obj_l;
            out[3] = (float)cls_l;
            g_acc[0] = 0.0; g_acc[1] = 0.0; g_acc[2] = 0.0; g_acc[3] = 0.0;
            g_cnt = 0u; g_wcnt = 0u; g_done = 0u; g_done2 = 0u;
        }
    }
}

extern "C" void kernel_launch(void* const* d_in, const int* in_sizes, int n_in,
                              void* d_out, int out_size) {
    const float* p3_cls  = (const float*)d_in[0];
    const float* p3_reg  = (const float*)d_in[1];
    const float* p3_obj  = (const float*)d_in[2];
    const float* p4_cls  = (const float*)d_in[3];
    const float* p4_reg  = (const float*)d_in[4];
    const float* p4_obj  = (const float*)d_in[5];
    const float* p5_cls  = (const float*)d_in[6];
    const float* p5_reg  = (const float*)d_in[7];
    const float* p5_obj  = (const float*)d_in[8];
    const float* targets = (const float*)d_in[9];

    k_main<<<NBLK, NTHR>>>(p3_cls, p3_reg, p3_obj,
                           p4_cls, p4_reg, p4_obj,
                           p5_cls, p5_reg, p5_obj,
                           targets, (float*)d_out);
}